// round 1
// baseline (speedup 1.0000x reference)
#include <cuda_runtime.h>
#include <math.h>

#define Bc 4
#define Sc 1024
#define Dm 1024
#define Hc 16
#define Dk 64

// -------- device scratch (allocation-free: static device globals) --------
__device__ float g_Q[Bc * Hc * Sc * Dk];   // 16 MB, [b,h,s,d], pre-scaled by 1/8
__device__ float g_K[Bc * Hc * Sc * Dk];   // 16 MB
__device__ float g_V[Bc * Hc * Sc * Dk];   // 16 MB
__device__ float g_ctx[Bc * Sc * Dm];      // 16 MB, [b,s,h*64+d]
__device__ float g_X[Bc * Sc * Dm];        // 16 MB, pre-LN activations

// ===========================================================================
// Generic fp32 SGEMM: C = (A[M,1024] @ W[1024,1024] + bias) * scale  (+ residual)
// MODE 0: scatter to [b,h,s,d] layout (QKV projections)
// MODE 1: row-major out = acc + bias + residual (output projection + residual)
// BM=BN=128, BK=8, 256 threads, 8x8 microtile.
// ===========================================================================
template <int MODE>
__global__ __launch_bounds__(256) void gemm_kernel(
    const float* __restrict__ A, const float* __restrict__ W,
    const float* __restrict__ bias, const float* __restrict__ residual,
    float* __restrict__ C, float scale)
{
    __shared__ float As[8][128];
    __shared__ float Bs[8][128];

    const int m0 = blockIdx.y * 128;
    const int n0 = blockIdx.x * 128;
    const int tid = threadIdx.x;
    const int tr = tid >> 4;          // 0..15
    const int tc = tid & 15;          // 0..15

    const int arow = tid >> 1;        // 0..127
    const int ac4  = (tid & 1) * 4;   // 0 or 4
    const int brow = tid >> 5;        // 0..7
    const int bc4  = (tid & 31) * 4;  // 0..124

    float acc[8][8];
#pragma unroll
    for (int i = 0; i < 8; i++)
#pragma unroll
        for (int j = 0; j < 8; j++) acc[i][j] = 0.f;

    for (int k0 = 0; k0 < 1024; k0 += 8) {
        float4 av = *(const float4*)&A[(size_t)(m0 + arow) * 1024 + k0 + ac4];
        As[ac4 + 0][arow] = av.x;
        As[ac4 + 1][arow] = av.y;
        As[ac4 + 2][arow] = av.z;
        As[ac4 + 3][arow] = av.w;
        *(float4*)&Bs[brow][bc4] =
            *(const float4*)&W[(size_t)(k0 + brow) * 1024 + n0 + bc4];
        __syncthreads();

#pragma unroll
        for (int kk = 0; kk < 8; kk++) {
            float ra[8], rb[8];
            *(float4*)&ra[0] = *(float4*)&As[kk][tr * 8];
            *(float4*)&ra[4] = *(float4*)&As[kk][tr * 8 + 4];
            *(float4*)&rb[0] = *(float4*)&Bs[kk][tc * 8];
            *(float4*)&rb[4] = *(float4*)&Bs[kk][tc * 8 + 4];
#pragma unroll
            for (int i = 0; i < 8; i++)
#pragma unroll
                for (int j = 0; j < 8; j++) acc[i][j] += ra[i] * rb[j];
        }
        __syncthreads();
    }

#pragma unroll
    for (int i = 0; i < 8; i++) {
        const int m = m0 + tr * 8 + i;
#pragma unroll
        for (int j = 0; j < 8; j++) {
            const int n = n0 + tc * 8 + j;
            float v = acc[i][j] + bias[n];
            if (MODE == 0) {
                const int b = m >> 10, s = m & 1023, h = n >> 6, d = n & 63;
                C[((size_t)(b * Hc + h) * Sc + s) * Dk + d] = v * scale;
            } else {
                C[(size_t)m * 1024 + n] = v + residual[(size_t)m * 1024 + n];
            }
        }
    }
}

// ===========================================================================
// Attention: one block handles 32 q rows for one (b,h).
// scores (32x1024) in dynamic smem -> mask -> softmax -> write attn -> ctx.
// ===========================================================================
__global__ __launch_bounds__(256) void attn_kernel(
    const int* __restrict__ mask, float* __restrict__ attn_out)
{
    extern __shared__ float sm[];
    float* sS  = sm;                  // 32*1024
    float* sQ  = sm + 32 * 1024;      // 32*64
    float* sKV = sQ + 32 * 64;        // 64*64

    const int b  = blockIdx.z;
    const int h  = blockIdx.y;
    const int q0 = blockIdx.x * 32;
    const int tid = threadIdx.x;

    const float* Qb = g_Q + ((size_t)(b * Hc + h) * Sc + q0) * Dk;
    const float* Kb = g_K + (size_t)(b * Hc + h) * Sc * Dk;
    const float* Vb = g_V + (size_t)(b * Hc + h) * Sc * Dk;

    // load Q tile (32x64)
    for (int i = tid; i < 32 * 64 / 4; i += 256)
        ((float4*)sQ)[i] = ((const float4*)Qb)[i];

    const int tq = tid >> 4;   // 0..15 -> 2 q rows each
    const int tk = tid & 15;   // 0..15 -> 4 k cols each

    // ---- scores: S = (Q/8) @ K^T, masked ----
    for (int kt = 0; kt < 16; kt++) {
        __syncthreads();
        for (int i = tid; i < 64 * 64 / 4; i += 256)
            ((float4*)sKV)[i] = ((const float4*)(Kb + (size_t)kt * 64 * 64))[i];
        __syncthreads();

        float acc0[4] = {0, 0, 0, 0}, acc1[4] = {0, 0, 0, 0};
#pragma unroll
        for (int d = 0; d < 64; d += 4) {
            float4 qa = *(float4*)&sQ[(tq * 2 + 0) * 64 + d];
            float4 qb = *(float4*)&sQ[(tq * 2 + 1) * 64 + d];
#pragma unroll
            for (int j = 0; j < 4; j++) {
                float4 kv = *(float4*)&sKV[(tk * 4 + j) * 64 + d];
                acc0[j] += qa.x * kv.x + qa.y * kv.y + qa.z * kv.z + qa.w * kv.w;
                acc1[j] += qb.x * kv.x + qb.y * kv.y + qb.z * kv.z + qb.w * kv.w;
            }
        }
#pragma unroll
        for (int j = 0; j < 4; j++) {
            const int kg = kt * 64 + tk * 4 + j;
            const bool msk = (mask[b * Sc + kg] == 0);
            sS[(tq * 2 + 0) * 1024 + kg] = msk ? -1e9f : acc0[j];
            sS[(tq * 2 + 1) * 1024 + kg] = msk ? -1e9f : acc1[j];
        }
    }
    __syncthreads();

    // ---- softmax: warp w handles rows 4w..4w+3 ----
    const int warp = tid >> 5, lane = tid & 31;
    for (int r = 0; r < 4; r++) {
        float* row = sS + (warp * 4 + r) * 1024;
        float mx = -3.4e38f;
        for (int k = lane; k < 1024; k += 32) mx = fmaxf(mx, row[k]);
#pragma unroll
        for (int o = 16; o; o >>= 1) mx = fmaxf(mx, __shfl_xor_sync(~0u, mx, o));
        float sum = 0.f;
        for (int k = lane; k < 1024; k += 32) {
            float e = expf(row[k] - mx);
            row[k] = e;
            sum += e;
        }
#pragma unroll
        for (int o = 16; o; o >>= 1) sum += __shfl_xor_sync(~0u, sum, o);
        const float inv = 1.f / sum;
        for (int k = lane; k < 1024; k += 32) row[k] *= inv;
    }
    __syncthreads();

    // ---- write attn (coalesced float4) ----
    float* ao = attn_out + ((size_t)(b * Hc + h) * Sc + q0) * 1024;
    for (int i = tid; i < 32 * 1024 / 4; i += 256)
        ((float4*)ao)[i] = ((float4*)sS)[i];

    // ---- ctx = attn @ V  (32x64 per block) ----
    const int cq = tid >> 3;           // 0..31
    const int d0 = (tid & 7) * 8;      // 0..56
    float cacc[8] = {0, 0, 0, 0, 0, 0, 0, 0};
    for (int kt = 0; kt < 16; kt++) {
        __syncthreads();
        for (int i = tid; i < 64 * 64 / 4; i += 256)
            ((float4*)sKV)[i] = ((const float4*)(Vb + (size_t)kt * 64 * 64))[i];
        __syncthreads();
#pragma unroll 8
        for (int kk = 0; kk < 64; kk++) {
            const float p = sS[cq * 1024 + kt * 64 + kk];
            float4 v0 = *(float4*)&sKV[kk * 64 + d0];
            float4 v1 = *(float4*)&sKV[kk * 64 + d0 + 4];
            cacc[0] += p * v0.x; cacc[1] += p * v0.y;
            cacc[2] += p * v0.z; cacc[3] += p * v0.w;
            cacc[4] += p * v1.x; cacc[5] += p * v1.y;
            cacc[6] += p * v1.z; cacc[7] += p * v1.w;
        }
    }
    float* co = g_ctx + ((size_t)b * Sc + q0 + cq) * Dm + h * Dk + d0;
#pragma unroll
    for (int j = 0; j < 8; j++) co[j] = cacc[j];
}

// ===========================================================================
// LayerNorm over last dim (1024), two-pass, one block per row.
// ===========================================================================
__global__ __launch_bounds__(256) void ln_kernel(
    const float* __restrict__ X, const float* __restrict__ gamma,
    const float* __restrict__ beta, float* __restrict__ out)
{
    __shared__ float red1[8];
    __shared__ float red2[8];
    const int row = blockIdx.x;
    const int tid = threadIdx.x;
    const float* x = X + (size_t)row * 1024;

    float v[4];
    float s = 0.f;
#pragma unroll
    for (int i = 0; i < 4; i++) { v[i] = x[tid + i * 256]; s += v[i]; }
#pragma unroll
    for (int o = 16; o; o >>= 1) s += __shfl_xor_sync(~0u, s, o);
    if ((tid & 31) == 0) red1[tid >> 5] = s;
    __syncthreads();
    if (tid < 32) {
        float t = (tid < 8) ? red1[tid] : 0.f;
#pragma unroll
        for (int o = 4; o; o >>= 1) t += __shfl_xor_sync(~0u, t, o);
        if (tid == 0) red1[0] = t;
    }
    __syncthreads();
    const float mu = red1[0] * (1.f / 1024.f);

    float ss = 0.f;
#pragma unroll
    for (int i = 0; i < 4; i++) { float d = v[i] - mu; ss += d * d; }
#pragma unroll
    for (int o = 16; o; o >>= 1) ss += __shfl_xor_sync(~0u, ss, o);
    if ((tid & 31) == 0) red2[tid >> 5] = ss;
    __syncthreads();
    if (tid < 32) {
        float t = (tid < 8) ? red2[tid] : 0.f;
#pragma unroll
        for (int o = 4; o; o >>= 1) t += __shfl_xor_sync(~0u, t, o);
        if (tid == 0) red2[0] = t;
    }
    __syncthreads();
    const float var = red2[0] * (1.f / 1024.f);
    const float rs = rsqrtf(var + 1e-5f);

#pragma unroll
    for (int i = 0; i < 4; i++) {
        const int c = tid + i * 256;
        out[(size_t)row * 1024 + c] = (v[i] - mu) * rs * gamma[c] + beta[c];
    }
}

// ===========================================================================
// Launch
// ===========================================================================
extern "C" void kernel_launch(void* const* d_in, const int* in_sizes, int n_in,
                              void* d_out, int out_size)
{
    const float* memory = (const float*)d_in[0];
    const float* dec    = (const float*)d_in[1];
    const int*   mask   = (const int*)d_in[2];
    const float* Wq = (const float*)d_in[3];
    const float* bq = (const float*)d_in[4];
    const float* Wk = (const float*)d_in[5];
    const float* bk = (const float*)d_in[6];
    const float* Wv = (const float*)d_in[7];
    const float* bv = (const float*)d_in[8];
    const float* Wo = (const float*)d_in[9];
    const float* bo = (const float*)d_in[10];
    const float* gamma = (const float*)d_in[11];
    const float* beta  = (const float*)d_in[12];

    float* out  = (float*)d_out;
    float* attn = out + (size_t)Bc * Sc * Dm;   // tuple: (out, attn) concatenated

    void *pQ, *pK, *pV, *pCtx, *pX;
    cudaGetSymbolAddress(&pQ, g_Q);
    cudaGetSymbolAddress(&pK, g_K);
    cudaGetSymbolAddress(&pV, g_V);
    cudaGetSymbolAddress(&pCtx, g_ctx);
    cudaGetSymbolAddress(&pX, g_X);

    const dim3 gg(8, 32), gt(256);

    // QKV projections (Q pre-scaled by 1/sqrt(64) = 0.125)
    gemm_kernel<0><<<gg, gt>>>(memory, Wq, bq, nullptr, (float*)pQ, 0.125f);
    gemm_kernel<0><<<gg, gt>>>(memory, Wk, bk, nullptr, (float*)pK, 1.0f);
    gemm_kernel<0><<<gg, gt>>>(dec,    Wv, bv, nullptr, (float*)pV, 1.0f);

    // attention
    const int smem = (32 * 1024 + 32 * 64 + 64 * 64) * sizeof(float);  // 139648 B
    cudaFuncSetAttribute(attn_kernel, cudaFuncAttributeMaxDynamicSharedMemorySize, smem);
    attn_kernel<<<dim3(32, Hc, Bc), 256, smem>>>(mask, attn);

    // output projection + residual, then LayerNorm
    gemm_kernel<1><<<gg, gt>>>((const float*)pCtx, Wo, bo, memory, (float*)pX, 1.0f);
    ln_kernel<<<Bc * Sc, 256>>>((const float*)pX, gamma, beta, out);
}

// round 3
// speedup vs baseline: 1.0827x; 1.0827x over previous
#include <cuda_runtime.h>
#include <cuda_bf16.h>
#include <cstdint>
#include <math.h>

#define Bc 4
#define Sc 1024
#define Dm 1024
#define Hc 16
#define Dk 64

// -------- device scratch (allocation-free: static device globals) --------
__device__ float g_Q[Bc * Hc * Sc * Dk];   // [b,h,s,d], pre-scaled by 1/8
__device__ float g_K[Bc * Hc * Sc * Dk];
__device__ float g_V[Bc * Hc * Sc * Dk];
__device__ float g_ctx[Bc * Sc * Dm];      // [b,s,h*64+d]
__device__ float g_X[Bc * Sc * Dm];        // pre-LN activations

// bf16 split scratch
__device__ __align__(256) unsigned short g_mh[4194304], g_ml[4194304];   // memory hi/lo
__device__ __align__(256) unsigned short g_dh[4194304], g_dl[4194304];   // decoder hi/lo
__device__ __align__(256) unsigned short g_ch[4194304], g_cl[4194304];   // ctx hi/lo
__device__ __align__(256) unsigned short g_WqTh[1048576], g_WqTl[1048576];
__device__ __align__(256) unsigned short g_WkTh[1048576], g_WkTl[1048576];
__device__ __align__(256) unsigned short g_WvTh[1048576], g_WvTl[1048576];
__device__ __align__(256) unsigned short g_WoTh[1048576], g_WoTl[1048576];

// ======================== PTX helpers (base sm_80+ ISA only) ==============
__device__ __forceinline__ uint32_t smem_to_u32(const void* p) {
    uint32_t a;
    asm("{ .reg .u64 t; cvta.to.shared.u64 t, %1; cvt.u32.u64 %0, t; }"
        : "=r"(a) : "l"(p));
    return a;
}

#define CP_ASYNC16(sm, gp) \
    asm volatile("cp.async.cg.shared.global [%0], [%1], 16;" \
        :: "r"(sm), "l"(gp) : "memory")
#define CP_COMMIT() asm volatile("cp.async.commit_group;" ::: "memory")
#define CP_WAIT0()  asm volatile("cp.async.wait_group 0;" ::: "memory")

#define LDMATRIX_X4(r0, r1, r2, r3, addr) \
    asm volatile("ldmatrix.sync.aligned.m8n8.x4.shared.b16 {%0,%1,%2,%3}, [%4];" \
        : "=r"(r0), "=r"(r1), "=r"(r2), "=r"(r3) : "r"(addr))

#define MMA16816(C, A, B) \
    asm volatile("mma.sync.aligned.m16n8k16.row.col.f32.bf16.bf16.f32 " \
        "{%0,%1,%2,%3}, {%4,%5,%6,%7}, {%8,%9}, {%0,%1,%2,%3};" \
        : "+f"((C)[0]), "+f"((C)[1]), "+f"((C)[2]), "+f"((C)[3]) \
        : "r"((A)[0]), "r"((A)[1]), "r"((A)[2]), "r"((A)[3]), \
          "r"((B)[0]), "r"((B)[1]))

// ===========================================================================
// split kernel: fp32 -> bf16 hi + bf16 lo
// ===========================================================================
__global__ __launch_bounds__(256) void split_kernel(
    const float* __restrict__ x, unsigned short* __restrict__ hi,
    unsigned short* __restrict__ lo, int n4)
{
    int i = blockIdx.x * 256 + threadIdx.x;
    if (i >= n4) return;
    float4 v = ((const float4*)x)[i];
    float f[4] = {v.x, v.y, v.z, v.w};
#pragma unroll
    for (int j = 0; j < 4; j++) {
        __nv_bfloat16 h = __float2bfloat16_rn(f[j]);
        __nv_bfloat16 l = __float2bfloat16_rn(f[j] - __bfloat162float(h));
        hi[i * 4 + j] = __bfloat16_as_ushort(h);
        lo[i * 4 + j] = __bfloat16_as_ushort(l);
    }
}

// ===========================================================================
// transpose+split kernel: W[k][n] fp32 -> WT_hi[n][k], WT_lo[n][k] bf16
// ===========================================================================
__global__ __launch_bounds__(256) void transsplit_kernel(
    const float* __restrict__ W, unsigned short* __restrict__ hiT,
    unsigned short* __restrict__ loT)
{
    __shared__ unsigned short sh[64][68];
    __shared__ unsigned short sl[64][68];
    const int k0 = blockIdx.y << 6, n0 = blockIdx.x << 6;
    const int r = threadIdx.x >> 4, c = (threadIdx.x & 15) << 2;
#pragma unroll
    for (int it = 0; it < 4; it++) {
        int row = r + it * 16;
        float4 v = *(const float4*)&W[(size_t)(k0 + row) * 1024 + n0 + c];
        float f[4] = {v.x, v.y, v.z, v.w};
#pragma unroll
        for (int j = 0; j < 4; j++) {
            __nv_bfloat16 h = __float2bfloat16_rn(f[j]);
            __nv_bfloat16 l = __float2bfloat16_rn(f[j] - __bfloat162float(h));
            sh[row][c + j] = __bfloat16_as_ushort(h);
            sl[row][c + j] = __bfloat16_as_ushort(l);
        }
    }
    __syncthreads();
#pragma unroll
    for (int it = 0; it < 4; it++) {
        int nn = r + it * 16;
#pragma unroll
        for (int j = 0; j < 4; j++) {
            hiT[(size_t)(n0 + nn) * 1024 + k0 + c + j] = sh[c + j][nn];
            loT[(size_t)(n0 + nn) * 1024 + k0 + c + j] = sl[c + j][nn];
        }
    }
}

// ===========================================================================
// HMMA GEMM via mma.sync bf16 (3-product split): 128x128 tile, BK=64,
// cp.async double-buffered smem, 256 threads, warp grid 4(M) x 2(N),
// each warp computes 32x64.
// MODE 0: scatter [b,h,s,d] with (acc+bias)*scale
// MODE 1: row-major, acc + bias + residual
// ===========================================================================
#define GT_ROW   72                    // padded row stride (bf16 units), 144 B
#define GT_TILE  (128 * GT_ROW)        // bf16 units per tile
#define GT_TILEB (GT_TILE * 2)         // 18432 bytes
#define GT_STAGEB (4 * GT_TILEB)       // 73728 bytes
#define GT_SMEM_SZ (2 * GT_STAGEB)     // 147456 bytes

template <int MODE>
__global__ __launch_bounds__(256, 1)
void gemm_mma(const unsigned short* __restrict__ Ah, const unsigned short* __restrict__ Al,
              const unsigned short* __restrict__ Bh, const unsigned short* __restrict__ Bl,
              const float* __restrict__ bias, const float* __restrict__ residual,
              float* __restrict__ C, float scale)
{
    extern __shared__ char smem[];
    const uint32_t sb = smem_to_u32(smem);
    const int tid = threadIdx.x;
    const int wid = tid >> 5, lane = tid & 31;
    const int wm = wid & 3, wn = wid >> 2;
    const int m0 = blockIdx.y * 128, n0 = blockIdx.x * 128;

    // ---- per-thread global/smem addressing for the copy ----
    const int crow = tid >> 1;              // 0..127
    const int cseg = (tid & 1) * 4;         // 0 or 4 (of 8 16B segs per row)
    const unsigned short* gsrc[4] = {
        Ah + (size_t)(m0 + crow) * 1024, Al + (size_t)(m0 + crow) * 1024,
        Bh + (size_t)(n0 + crow) * 1024, Bl + (size_t)(n0 + crow) * 1024};
    const uint32_t srow = crow * (GT_ROW * 2) + cseg * 16;  // byte offset in tile

    auto load_stage = [&](int stg, int k0) {
#pragma unroll
        for (int tile = 0; tile < 4; tile++) {
            const unsigned short* g = gsrc[tile] + k0 + cseg * 8;
            uint32_t s = sb + stg * GT_STAGEB + tile * GT_TILEB + srow;
#pragma unroll
            for (int i = 0; i < 4; i++)
                CP_ASYNC16(s + i * 16, g + i * 8);
        }
        CP_COMMIT();
    };

    // ---- accumulators ----
    float acc[2][8][4];
#pragma unroll
    for (int mt = 0; mt < 2; mt++)
#pragma unroll
        for (int nt = 0; nt < 8; nt++)
#pragma unroll
            for (int j = 0; j < 4; j++) acc[mt][nt][j] = 0.f;

    // ldmatrix lane addressing: g = lane>>3 selects (rowoff, koff) quadrant
    const int lg = lane >> 3, lr = lane & 7;
    const int rowoff = (lg & 1) * 8 + lr;       // within 16-row tile
    const uint32_t kquad = (lg >> 1) * 16;      // 0 or 16 bytes (k half)

    load_stage(0, 0);
    CP_WAIT0();
    __syncthreads();

    for (int t = 0; t < 16; t++) {
        const int buf = t & 1;
        if (t + 1 < 16) load_stage(buf ^ 1, (t + 1) * 64);

        const uint32_t stg = sb + buf * GT_STAGEB;
#pragma unroll
        for (int ks = 0; ks < 4; ks++) {
            const uint32_t kb = ks * 32 + kquad;   // byte offset along K
            // --- A fragments (hi, lo) for 2 m-tiles ---
            uint32_t ah[2][4], al[2][4];
#pragma unroll
            for (int mt = 0; mt < 2; mt++) {
                uint32_t r = (wm * 32 + mt * 16 + rowoff) * (GT_ROW * 2) + kb;
                LDMATRIX_X4(ah[mt][0], ah[mt][1], ah[mt][2], ah[mt][3], stg + r);
                LDMATRIX_X4(al[mt][0], al[mt][1], al[mt][2], al[mt][3],
                            stg + GT_TILEB + r);
            }
            // --- B fragments (hi, lo) for 8 n-tiles (pairs via x4) ---
            uint32_t bh[8][2], bl[8][2];
#pragma unroll
            for (int p = 0; p < 4; p++) {
                uint32_t r = (wn * 64 + p * 16 + rowoff) * (GT_ROW * 2) + kb;
                LDMATRIX_X4(bh[2 * p][0], bh[2 * p + 1][0],
                            bh[2 * p][1], bh[2 * p + 1][1],
                            stg + 2 * GT_TILEB + r);
                LDMATRIX_X4(bl[2 * p][0], bl[2 * p + 1][0],
                            bl[2 * p][1], bl[2 * p + 1][1],
                            stg + 3 * GT_TILEB + r);
            }
            // --- 3-product MMAs ---
#pragma unroll
            for (int mt = 0; mt < 2; mt++)
#pragma unroll
                for (int nt = 0; nt < 8; nt++) {
                    MMA16816(acc[mt][nt], ah[mt], bh[nt]);
                    MMA16816(acc[mt][nt], ah[mt], bl[nt]);
                    MMA16816(acc[mt][nt], al[mt], bh[nt]);
                }
        }
        if (t + 1 < 16) CP_WAIT0();
        __syncthreads();
    }

    // ---- epilogue: regs -> gmem (float2), fused bias/scale/residual ----
    const int erow = lane >> 2;               // 0..7
    const int ecol = (lane & 3) * 2;          // 0,2,4,6
#pragma unroll
    for (int mt = 0; mt < 2; mt++) {
#pragma unroll
        for (int nt = 0; nt < 8; nt++) {
            const int n = n0 + wn * 64 + nt * 8 + ecol;
            const float b0 = bias[n], b1 = bias[n + 1];
#pragma unroll
            for (int half = 0; half < 2; half++) {
                const int m = m0 + wm * 32 + mt * 16 + erow + half * 8;
                float2 v;
                v.x = acc[mt][nt][half * 2 + 0] + b0;
                v.y = acc[mt][nt][half * 2 + 1] + b1;
                if (MODE == 0) {
                    v.x *= scale; v.y *= scale;
                    const int b = m >> 10, s = m & 1023, h = n >> 6, d = n & 63;
                    *(float2*)&C[((size_t)(b * Hc + h) * Sc + s) * Dk + d] = v;
                } else {
                    const size_t idx = (size_t)m * 1024 + n;
                    float2 r = *(const float2*)&residual[idx];
                    v.x += r.x; v.y += r.y;
                    *(float2*)&C[idx] = v;
                }
            }
        }
    }
}

// ===========================================================================
// Attention (unchanged): one block = 32 q rows for one (b,h).
// ===========================================================================
__global__ __launch_bounds__(256) void attn_kernel(
    const int* __restrict__ mask, float* __restrict__ attn_out)
{
    extern __shared__ float sm[];
    float* sS  = sm;                  // 32*1024
    float* sQ  = sm + 32 * 1024;      // 32*64
    float* sKV = sQ + 32 * 64;        // 64*64

    const int b  = blockIdx.z;
    const int h  = blockIdx.y;
    const int q0 = blockIdx.x * 32;
    const int tid = threadIdx.x;

    const float* Qb = g_Q + ((size_t)(b * Hc + h) * Sc + q0) * Dk;
    const float* Kb = g_K + (size_t)(b * Hc + h) * Sc * Dk;
    const float* Vb = g_V + (size_t)(b * Hc + h) * Sc * Dk;

    for (int i = tid; i < 32 * 64 / 4; i += 256)
        ((float4*)sQ)[i] = ((const float4*)Qb)[i];

    const int tq = tid >> 4;
    const int tk = tid & 15;

    for (int kt = 0; kt < 16; kt++) {
        __syncthreads();
        for (int i = tid; i < 64 * 64 / 4; i += 256)
            ((float4*)sKV)[i] = ((const float4*)(Kb + (size_t)kt * 64 * 64))[i];
        __syncthreads();

        float acc0[4] = {0, 0, 0, 0}, acc1[4] = {0, 0, 0, 0};
#pragma unroll
        for (int d = 0; d < 64; d += 4) {
            float4 qa = *(float4*)&sQ[(tq * 2 + 0) * 64 + d];
            float4 qb = *(float4*)&sQ[(tq * 2 + 1) * 64 + d];
#pragma unroll
            for (int j = 0; j < 4; j++) {
                float4 kv = *(float4*)&sKV[(tk * 4 + j) * 64 + d];
                acc0[j] += qa.x * kv.x + qa.y * kv.y + qa.z * kv.z + qa.w * kv.w;
                acc1[j] += qb.x * kv.x + qb.y * kv.y + qb.z * kv.z + qb.w * kv.w;
            }
        }
#pragma unroll
        for (int j = 0; j < 4; j++) {
            const int kg = kt * 64 + tk * 4 + j;
            const bool msk = (mask[b * Sc + kg] == 0);
            sS[(tq * 2 + 0) * 1024 + kg] = msk ? -1e9f : acc0[j];
            sS[(tq * 2 + 1) * 1024 + kg] = msk ? -1e9f : acc1[j];
        }
    }
    __syncthreads();

    const int warp = tid >> 5, lane = tid & 31;
    for (int r = 0; r < 4; r++) {
        float* rowp = sS + (warp * 4 + r) * 1024;
        float mx = -3.4e38f;
        for (int k = lane; k < 1024; k += 32) mx = fmaxf(mx, rowp[k]);
#pragma unroll
        for (int o = 16; o; o >>= 1) mx = fmaxf(mx, __shfl_xor_sync(~0u, mx, o));
        float sum = 0.f;
        for (int k = lane; k < 1024; k += 32) {
            float e = expf(rowp[k] - mx);
            rowp[k] = e;
            sum += e;
        }
#pragma unroll
        for (int o = 16; o; o >>= 1) sum += __shfl_xor_sync(~0u, sum, o);
        const float inv = 1.f / sum;
        for (int k = lane; k < 1024; k += 32) rowp[k] *= inv;
    }
    __syncthreads();

    float* ao = attn_out + ((size_t)(b * Hc + h) * Sc + q0) * 1024;
    for (int i = tid; i < 32 * 1024 / 4; i += 256)
        ((float4*)ao)[i] = ((float4*)sS)[i];

    const int cq = tid >> 3;
    const int d0 = (tid & 7) * 8;
    float cacc[8] = {0, 0, 0, 0, 0, 0, 0, 0};
    for (int kt = 0; kt < 16; kt++) {
        __syncthreads();
        for (int i = tid; i < 64 * 64 / 4; i += 256)
            ((float4*)sKV)[i] = ((const float4*)(Vb + (size_t)kt * 64 * 64))[i];
        __syncthreads();
#pragma unroll 8
        for (int kk = 0; kk < 64; kk++) {
            const float p = sS[cq * 1024 + kt * 64 + kk];
            float4 v0 = *(float4*)&sKV[kk * 64 + d0];
            float4 v1 = *(float4*)&sKV[kk * 64 + d0 + 4];
            cacc[0] += p * v0.x; cacc[1] += p * v0.y;
            cacc[2] += p * v0.z; cacc[3] += p * v0.w;
            cacc[4] += p * v1.x; cacc[5] += p * v1.y;
            cacc[6] += p * v1.z; cacc[7] += p * v1.w;
        }
    }
    float* co = g_ctx + ((size_t)b * Sc + q0 + cq) * Dm + h * Dk + d0;
#pragma unroll
    for (int j = 0; j < 8; j++) co[j] = cacc[j];
}

// ===========================================================================
// LayerNorm (unchanged)
// ===========================================================================
__global__ __launch_bounds__(256) void ln_kernel(
    const float* __restrict__ X, const float* __restrict__ gamma,
    const float* __restrict__ beta, float* __restrict__ out)
{
    __shared__ float red1[8];
    __shared__ float red2[8];
    const int row = blockIdx.x;
    const int tid = threadIdx.x;
    const float* x = X + (size_t)row * 1024;

    float v[4];
    float s = 0.f;
#pragma unroll
    for (int i = 0; i < 4; i++) { v[i] = x[tid + i * 256]; s += v[i]; }
#pragma unroll
    for (int o = 16; o; o >>= 1) s += __shfl_xor_sync(~0u, s, o);
    if ((tid & 31) == 0) red1[tid >> 5] = s;
    __syncthreads();
    if (tid < 32) {
        float t = (tid < 8) ? red1[tid] : 0.f;
#pragma unroll
        for (int o = 4; o; o >>= 1) t += __shfl_xor_sync(~0u, t, o);
        if (tid == 0) red1[0] = t;
    }
    __syncthreads();
    const float mu = red1[0] * (1.f / 1024.f);

    float ss = 0.f;
#pragma unroll
    for (int i = 0; i < 4; i++) { float d = v[i] - mu; ss += d * d; }
#pragma unroll
    for (int o = 16; o; o >>= 1) ss += __shfl_xor_sync(~0u, ss, o);
    if ((tid & 31) == 0) red2[tid >> 5] = ss;
    __syncthreads();
    if (tid < 32) {
        float t = (tid < 8) ? red2[tid] : 0.f;
#pragma unroll
        for (int o = 4; o; o >>= 1) t += __shfl_xor_sync(~0u, t, o);
        if (tid == 0) red2[0] = t;
    }
    __syncthreads();
    const float var = red2[0] * (1.f / 1024.f);
    const float rs = rsqrtf(var + 1e-5f);

#pragma unroll
    for (int i = 0; i < 4; i++) {
        const int c = tid + i * 256;
        out[(size_t)row * 1024 + c] = (v[i] - mu) * rs * gamma[c] + beta[c];
    }
}

// ===========================================================================
// Launch
// ===========================================================================
extern "C" void kernel_launch(void* const* d_in, const int* in_sizes, int n_in,
                              void* d_out, int out_size)
{
    const float* memory = (const float*)d_in[0];
    const float* dec    = (const float*)d_in[1];
    const int*   mask   = (const int*)d_in[2];
    const float* Wq = (const float*)d_in[3];
    const float* bq = (const float*)d_in[4];
    const float* Wk = (const float*)d_in[5];
    const float* bk = (const float*)d_in[6];
    const float* Wv = (const float*)d_in[7];
    const float* bv = (const float*)d_in[8];
    const float* Wo = (const float*)d_in[9];
    const float* bo = (const float*)d_in[10];
    const float* gamma = (const float*)d_in[11];
    const float* beta  = (const float*)d_in[12];

    float* out  = (float*)d_out;
    float* attn = out + (size_t)Bc * Sc * Dm;

    void *pQ, *pK, *pV, *pCtx, *pX;
    cudaGetSymbolAddress(&pQ, g_Q);
    cudaGetSymbolAddress(&pK, g_K);
    cudaGetSymbolAddress(&pV, g_V);
    cudaGetSymbolAddress(&pCtx, g_ctx);
    cudaGetSymbolAddress(&pX, g_X);
    void *pmh, *pml, *pdh, *pdl, *pch, *pcl;
    cudaGetSymbolAddress(&pmh, g_mh); cudaGetSymbolAddress(&pml, g_ml);
    cudaGetSymbolAddress(&pdh, g_dh); cudaGetSymbolAddress(&pdl, g_dl);
    cudaGetSymbolAddress(&pch, g_ch); cudaGetSymbolAddress(&pcl, g_cl);
    void *pqh, *pql, *pkh, *pkl, *pvh, *pvl, *poh, *pol;
    cudaGetSymbolAddress(&pqh, g_WqTh); cudaGetSymbolAddress(&pql, g_WqTl);
    cudaGetSymbolAddress(&pkh, g_WkTh); cudaGetSymbolAddress(&pkl, g_WkTl);
    cudaGetSymbolAddress(&pvh, g_WvTh); cudaGetSymbolAddress(&pvl, g_WvTl);
    cudaGetSymbolAddress(&poh, g_WoTh); cudaGetSymbolAddress(&pol, g_WoTl);

    const int NACT4 = Bc * Sc * Dm / 4;

    // ---- prep: split activations, transpose+split weights ----
    split_kernel<<<NACT4 / 256, 256>>>(memory, (unsigned short*)pmh, (unsigned short*)pml, NACT4);
    split_kernel<<<NACT4 / 256, 256>>>(dec,    (unsigned short*)pdh, (unsigned short*)pdl, NACT4);
    transsplit_kernel<<<dim3(16, 16), 256>>>(Wq, (unsigned short*)pqh, (unsigned short*)pql);
    transsplit_kernel<<<dim3(16, 16), 256>>>(Wk, (unsigned short*)pkh, (unsigned short*)pkl);
    transsplit_kernel<<<dim3(16, 16), 256>>>(Wv, (unsigned short*)pvh, (unsigned short*)pvl);
    transsplit_kernel<<<dim3(16, 16), 256>>>(Wo, (unsigned short*)poh, (unsigned short*)pol);

    // ---- HMMA projections ----
    cudaFuncSetAttribute(gemm_mma<0>, cudaFuncAttributeMaxDynamicSharedMemorySize, GT_SMEM_SZ);
    cudaFuncSetAttribute(gemm_mma<1>, cudaFuncAttributeMaxDynamicSharedMemorySize, GT_SMEM_SZ);
    const dim3 gg(8, 32), gt(256);
    gemm_mma<0><<<gg, gt, GT_SMEM_SZ>>>((unsigned short*)pmh, (unsigned short*)pml,
                                        (unsigned short*)pqh, (unsigned short*)pql,
                                        bq, nullptr, (float*)pQ, 0.125f);
    gemm_mma<0><<<gg, gt, GT_SMEM_SZ>>>((unsigned short*)pmh, (unsigned short*)pml,
                                        (unsigned short*)pkh, (unsigned short*)pkl,
                                        bk, nullptr, (float*)pK, 1.0f);
    gemm_mma<0><<<gg, gt, GT_SMEM_SZ>>>((unsigned short*)pdh, (unsigned short*)pdl,
                                        (unsigned short*)pvh, (unsigned short*)pvl,
                                        bv, nullptr, (float*)pV, 1.0f);

    // ---- attention ----
    const int smem = (32 * 1024 + 32 * 64 + 64 * 64) * sizeof(float);
    cudaFuncSetAttribute(attn_kernel, cudaFuncAttributeMaxDynamicSharedMemorySize, smem);
    attn_kernel<<<dim3(32, Hc, Bc), 256, smem>>>(mask, attn);

    // ---- output projection + residual (HMMA), then LayerNorm ----
    split_kernel<<<NACT4 / 256, 256>>>((const float*)pCtx, (unsigned short*)pch,
                                       (unsigned short*)pcl, NACT4);
    gemm_mma<1><<<gg, gt, GT_SMEM_SZ>>>((unsigned short*)pch, (unsigned short*)pcl,
                                        (unsigned short*)poh, (unsigned short*)pol,
                                        bo, memory, (float*)pX, 1.0f);
    ln_kernel<<<Bc * Sc, 256>>>((const float*)pX, gamma, beta, out);
}

// round 4
// speedup vs baseline: 5.0121x; 4.6292x over previous
#include <cuda_runtime.h>
#include <cuda_bf16.h>
#include <cuda_fp16.h>
#include <cstdint>
#include <math.h>

#define Bc 4
#define Sc 1024
#define Dm 1024
#define Hc 16
#define Dk 64

// -------- device scratch (allocation-free: static device globals) --------
__device__ float g_X[Bc * Sc * Dm];        // pre-LN activations

// bf16 split scratch
__device__ __align__(256) unsigned short g_mh[4194304], g_ml[4194304];   // memory hi/lo
__device__ __align__(256) unsigned short g_dh[4194304], g_dl[4194304];   // decoder hi/lo
__device__ __align__(256) unsigned short g_ch[4194304], g_cl[4194304];   // ctx hi/lo
__device__ __align__(256) unsigned short g_WqTh[1048576], g_WqTl[1048576];
__device__ __align__(256) unsigned short g_WkTh[1048576], g_WkTl[1048576];
__device__ __align__(256) unsigned short g_WvTh[1048576], g_WvTl[1048576];
__device__ __align__(256) unsigned short g_WoTh[1048576], g_WoTl[1048576];
// attention operands
__device__ __align__(256) unsigned short g_Qh[4194304], g_Ql[4194304];   // [b,h,s,d] bf16
__device__ __align__(256) unsigned short g_Kh[4194304], g_Kl[4194304];   // [b,h,s,d] bf16
__device__ __align__(256) __half g_VT[4194304];                          // [b,h,d,s] fp16

// ======================== PTX helpers (base sm_80+ ISA only) ==============
__device__ __forceinline__ uint32_t smem_to_u32(const void* p) {
    uint32_t a;
    asm("{ .reg .u64 t; cvta.to.shared.u64 t, %1; cvt.u32.u64 %0, t; }"
        : "=r"(a) : "l"(p));
    return a;
}

#define CP_ASYNC16(sm, gp) \
    asm volatile("cp.async.cg.shared.global [%0], [%1], 16;" \
        :: "r"(sm), "l"(gp) : "memory")
#define CP_COMMIT() asm volatile("cp.async.commit_group;" ::: "memory")
#define CP_WAIT0()  asm volatile("cp.async.wait_group 0;" ::: "memory")

#define LDMATRIX_X4(r0, r1, r2, r3, addr) \
    asm volatile("ldmatrix.sync.aligned.m8n8.x4.shared.b16 {%0,%1,%2,%3}, [%4];" \
        : "=r"(r0), "=r"(r1), "=r"(r2), "=r"(r3) : "r"(addr))

#define MMA16816(C, A, B) \
    asm volatile("mma.sync.aligned.m16n8k16.row.col.f32.bf16.bf16.f32 " \
        "{%0,%1,%2,%3}, {%4,%5,%6,%7}, {%8,%9}, {%0,%1,%2,%3};" \
        : "+f"((C)[0]), "+f"((C)[1]), "+f"((C)[2]), "+f"((C)[3]) \
        : "r"((A)[0]), "r"((A)[1]), "r"((A)[2]), "r"((A)[3]), \
          "r"((B)[0]), "r"((B)[1]))

#define MMA16816F16(C, A, B) \
    asm volatile("mma.sync.aligned.m16n8k16.row.col.f32.f16.f16.f32 " \
        "{%0,%1,%2,%3}, {%4,%5,%6,%7}, {%8,%9}, {%0,%1,%2,%3};" \
        : "+f"((C)[0]), "+f"((C)[1]), "+f"((C)[2]), "+f"((C)[3]) \
        : "r"((A)[0]), "r"((A)[1]), "r"((A)[2]), "r"((A)[3]), \
          "r"((B)[0]), "r"((B)[1]))

// ===========================================================================
// split kernel: fp32 -> bf16 hi + bf16 lo
// ===========================================================================
__global__ __launch_bounds__(256) void split_kernel(
    const float* __restrict__ x, unsigned short* __restrict__ hi,
    unsigned short* __restrict__ lo, int n4)
{
    int i = blockIdx.x * 256 + threadIdx.x;
    if (i >= n4) return;
    float4 v = ((const float4*)x)[i];
    float f[4] = {v.x, v.y, v.z, v.w};
#pragma unroll
    for (int j = 0; j < 4; j++) {
        __nv_bfloat16 h = __float2bfloat16_rn(f[j]);
        __nv_bfloat16 l = __float2bfloat16_rn(f[j] - __bfloat162float(h));
        hi[i * 4 + j] = __bfloat16_as_ushort(h);
        lo[i * 4 + j] = __bfloat16_as_ushort(l);
    }
}

// ===========================================================================
// transpose+split kernel: W[k][n] fp32 -> WT_hi[n][k], WT_lo[n][k] bf16
// ===========================================================================
__global__ __launch_bounds__(256) void transsplit_kernel(
    const float* __restrict__ W, unsigned short* __restrict__ hiT,
    unsigned short* __restrict__ loT)
{
    __shared__ unsigned short sh[64][68];
    __shared__ unsigned short sl[64][68];
    const int k0 = blockIdx.y << 6, n0 = blockIdx.x << 6;
    const int r = threadIdx.x >> 4, c = (threadIdx.x & 15) << 2;
#pragma unroll
    for (int it = 0; it < 4; it++) {
        int row = r + it * 16;
        float4 v = *(const float4*)&W[(size_t)(k0 + row) * 1024 + n0 + c];
        float f[4] = {v.x, v.y, v.z, v.w};
#pragma unroll
        for (int j = 0; j < 4; j++) {
            __nv_bfloat16 h = __float2bfloat16_rn(f[j]);
            __nv_bfloat16 l = __float2bfloat16_rn(f[j] - __bfloat162float(h));
            sh[row][c + j] = __bfloat16_as_ushort(h);
            sl[row][c + j] = __bfloat16_as_ushort(l);
        }
    }
    __syncthreads();
#pragma unroll
    for (int it = 0; it < 4; it++) {
        int nn = r + it * 16;
#pragma unroll
        for (int j = 0; j < 4; j++) {
            hiT[(size_t)(n0 + nn) * 1024 + k0 + c + j] = sh[c + j][nn];
            loT[(size_t)(n0 + nn) * 1024 + k0 + c + j] = sl[c + j][nn];
        }
    }
}

// ===========================================================================
// HMMA GEMM (bf16 3-product split), 128x128 tile, BK=64, double-buffered.
// MODE 0: Q/K proj -> bf16 hi/lo scatter [b,h,s,d], (acc+bias)*scale
// MODE 1: out proj -> fp32 row-major, acc + bias + residual
// MODE 2: V proj -> fp16 transposed [b,h,d,s], acc + bias
// ===========================================================================
#define GT_ROW   72
#define GT_TILEB (128 * GT_ROW * 2)    // 18432
#define GT_STAGEB (4 * GT_TILEB)       // 73728
#define GT_SMEM_SZ (2 * GT_STAGEB)     // 147456

template <int MODE>
__global__ __launch_bounds__(256, 1)
void gemm_mma(const unsigned short* __restrict__ Ah, const unsigned short* __restrict__ Al,
              const unsigned short* __restrict__ Bh, const unsigned short* __restrict__ Bl,
              const float* __restrict__ bias, const float* __restrict__ residual,
              void* __restrict__ C0, void* __restrict__ C1, float scale)
{
    extern __shared__ char smem[];
    const uint32_t sb = smem_to_u32(smem);
    const int tid = threadIdx.x;
    const int wid = tid >> 5, lane = tid & 31;
    const int wm = wid & 3, wn = wid >> 2;
    const int m0 = blockIdx.y * 128, n0 = blockIdx.x * 128;

    const int crow = tid >> 1;
    const int cseg = (tid & 1) * 4;
    const unsigned short* gsrc[4] = {
        Ah + (size_t)(m0 + crow) * 1024, Al + (size_t)(m0 + crow) * 1024,
        Bh + (size_t)(n0 + crow) * 1024, Bl + (size_t)(n0 + crow) * 1024};
    const uint32_t srow = crow * (GT_ROW * 2) + cseg * 16;

    auto load_stage = [&](int stg, int k0) {
#pragma unroll
        for (int tile = 0; tile < 4; tile++) {
            const unsigned short* g = gsrc[tile] + k0 + cseg * 8;
            uint32_t s = sb + stg * GT_STAGEB + tile * GT_TILEB + srow;
#pragma unroll
            for (int i = 0; i < 4; i++)
                CP_ASYNC16(s + i * 16, g + i * 8);
        }
        CP_COMMIT();
    };

    float acc[2][8][4];
#pragma unroll
    for (int mt = 0; mt < 2; mt++)
#pragma unroll
        for (int nt = 0; nt < 8; nt++)
#pragma unroll
            for (int j = 0; j < 4; j++) acc[mt][nt][j] = 0.f;

    const int lg = lane >> 3, lr = lane & 7;
    const int rowoff = (lg & 1) * 8 + lr;
    const uint32_t kquad = (lg >> 1) * 16;

    load_stage(0, 0);
    CP_WAIT0();
    __syncthreads();

    for (int t = 0; t < 16; t++) {
        const int buf = t & 1;
        if (t + 1 < 16) load_stage(buf ^ 1, (t + 1) * 64);

        const uint32_t stg = sb + buf * GT_STAGEB;
#pragma unroll
        for (int ks = 0; ks < 4; ks++) {
            const uint32_t kb = ks * 32 + kquad;
            uint32_t ah[2][4], al[2][4];
#pragma unroll
            for (int mt = 0; mt < 2; mt++) {
                uint32_t r = (wm * 32 + mt * 16 + rowoff) * (GT_ROW * 2) + kb;
                LDMATRIX_X4(ah[mt][0], ah[mt][1], ah[mt][2], ah[mt][3], stg + r);
                LDMATRIX_X4(al[mt][0], al[mt][1], al[mt][2], al[mt][3],
                            stg + GT_TILEB + r);
            }
            uint32_t bh[8][2], bl[8][2];
#pragma unroll
            for (int p = 0; p < 4; p++) {
                uint32_t r = (wn * 64 + p * 16 + rowoff) * (GT_ROW * 2) + kb;
                LDMATRIX_X4(bh[2 * p][0], bh[2 * p + 1][0],
                            bh[2 * p][1], bh[2 * p + 1][1],
                            stg + 2 * GT_TILEB + r);
                LDMATRIX_X4(bl[2 * p][0], bl[2 * p + 1][0],
                            bl[2 * p][1], bl[2 * p + 1][1],
                            stg + 3 * GT_TILEB + r);
            }
#pragma unroll
            for (int mt = 0; mt < 2; mt++)
#pragma unroll
                for (int nt = 0; nt < 8; nt++) {
                    MMA16816(acc[mt][nt], ah[mt], bh[nt]);
                    MMA16816(acc[mt][nt], ah[mt], bl[nt]);
                    MMA16816(acc[mt][nt], al[mt], bh[nt]);
                }
        }
        if (t + 1 < 16) CP_WAIT0();
        __syncthreads();
    }

    // ---- epilogue ----
    const int erow = lane >> 2;
    const int ecol = (lane & 3) * 2;
#pragma unroll
    for (int mt = 0; mt < 2; mt++) {
#pragma unroll
        for (int nt = 0; nt < 8; nt++) {
            const int n = n0 + wn * 64 + nt * 8 + ecol;
            const float b0 = bias[n], b1 = bias[n + 1];
#pragma unroll
            for (int half = 0; half < 2; half++) {
                const int m = m0 + wm * 32 + mt * 16 + erow + half * 8;
                float v0 = acc[mt][nt][half * 2 + 0] + b0;
                float v1 = acc[mt][nt][half * 2 + 1] + b1;
                if (MODE == 0) {
                    v0 *= scale; v1 *= scale;
                    const int bb = m >> 10, s = m & 1023, hh = n >> 6, d = n & 63;
                    const size_t idx = ((size_t)(bb * Hc + hh) * Sc + s) * Dk + d;
                    __nv_bfloat16 h0 = __float2bfloat16_rn(v0);
                    __nv_bfloat16 h1 = __float2bfloat16_rn(v1);
                    __nv_bfloat16 l0 = __float2bfloat16_rn(v0 - __bfloat162float(h0));
                    __nv_bfloat16 l1 = __float2bfloat16_rn(v1 - __bfloat162float(h1));
                    ushort2 uh; uh.x = __bfloat16_as_ushort(h0); uh.y = __bfloat16_as_ushort(h1);
                    ushort2 ul; ul.x = __bfloat16_as_ushort(l0); ul.y = __bfloat16_as_ushort(l1);
                    *(ushort2*)&((unsigned short*)C0)[idx] = uh;
                    *(ushort2*)&((unsigned short*)C1)[idx] = ul;
                } else if (MODE == 2) {
                    const int bb = m >> 10, s = m & 1023, hh = n >> 6, d = n & 63;
                    const size_t idx = ((size_t)(bb * Hc + hh) * Dk + d) * Sc + s;
                    ((__half*)C0)[idx] = __float2half_rn(v0);
                    ((__half*)C0)[idx + Sc] = __float2half_rn(v1);
                } else {
                    const size_t idx = (size_t)m * 1024 + n;
                    float2 r = *(const float2*)&residual[idx];
                    float2 v; v.x = v0 + r.x; v.y = v1 + r.y;
                    *(float2*)&((float*)C0)[idx] = v;
                }
            }
        }
    }
}

// ===========================================================================
// scores kernel: S[bh][m][n] = Q[bh][m][:] . K[bh][n][:]  (bf16 split, K=64)
// 128x128 tile per block, single smem stage, mask fused. grid (8, 8, 64)
// ===========================================================================
#define SC_SMEM_SZ (4 * GT_TILEB)   // 73728

__global__ __launch_bounds__(256, 1)
void scores_kernel(const int* __restrict__ mask, float* __restrict__ S)
{
    extern __shared__ char smem[];
    const uint32_t sb = smem_to_u32(smem);
    const int tid = threadIdx.x;
    const int wid = tid >> 5, lane = tid & 31;
    const int wm = wid & 3, wn = wid >> 2;
    const int bh = blockIdx.z, b = bh >> 4;
    const int m0 = blockIdx.y * 128, n0 = blockIdx.x * 128;

    const size_t base = (size_t)bh * (Sc * Dk);
    const int crow = tid >> 1;
    const int chalf = tid & 1;      // half-row (32 bf16 = 64B)
    const unsigned short* gsrc[4] = {
        g_Qh + base + (size_t)(m0 + crow) * 64 + chalf * 32,
        g_Ql + base + (size_t)(m0 + crow) * 64 + chalf * 32,
        g_Kh + base + (size_t)(n0 + crow) * 64 + chalf * 32,
        g_Kl + base + (size_t)(n0 + crow) * 64 + chalf * 32};
    const uint32_t srow = crow * (GT_ROW * 2) + chalf * 64;

#pragma unroll
    for (int tile = 0; tile < 4; tile++) {
        uint32_t s = sb + tile * GT_TILEB + srow;
#pragma unroll
        for (int i = 0; i < 4; i++)
            CP_ASYNC16(s + i * 16, gsrc[tile] + i * 8);
    }
    CP_COMMIT();

    float acc[2][8][4];
#pragma unroll
    for (int mt = 0; mt < 2; mt++)
#pragma unroll
        for (int nt = 0; nt < 8; nt++)
#pragma unroll
            for (int j = 0; j < 4; j++) acc[mt][nt][j] = 0.f;

    const int lg = lane >> 3, lr = lane & 7;
    const int rowoff = (lg & 1) * 8 + lr;
    const uint32_t kquad = (lg >> 1) * 16;

    CP_WAIT0();
    __syncthreads();

#pragma unroll
    for (int ks = 0; ks < 4; ks++) {
        const uint32_t kb = ks * 32 + kquad;
        uint32_t ah[2][4], al[2][4];
#pragma unroll
        for (int mt = 0; mt < 2; mt++) {
            uint32_t r = (wm * 32 + mt * 16 + rowoff) * (GT_ROW * 2) + kb;
            LDMATRIX_X4(ah[mt][0], ah[mt][1], ah[mt][2], ah[mt][3], sb + r);
            LDMATRIX_X4(al[mt][0], al[mt][1], al[mt][2], al[mt][3],
                        sb + GT_TILEB + r);
        }
        uint32_t bhf[8][2], blf[8][2];
#pragma unroll
        for (int p = 0; p < 4; p++) {
            uint32_t r = (wn * 64 + p * 16 + rowoff) * (GT_ROW * 2) + kb;
            LDMATRIX_X4(bhf[2 * p][0], bhf[2 * p + 1][0],
                        bhf[2 * p][1], bhf[2 * p + 1][1],
                        sb + 2 * GT_TILEB + r);
            LDMATRIX_X4(blf[2 * p][0], blf[2 * p + 1][0],
                        blf[2 * p][1], blf[2 * p + 1][1],
                        sb + 3 * GT_TILEB + r);
        }
#pragma unroll
        for (int mt = 0; mt < 2; mt++)
#pragma unroll
            for (int nt = 0; nt < 8; nt++) {
                MMA16816(acc[mt][nt], ah[mt], bhf[nt]);
                MMA16816(acc[mt][nt], ah[mt], blf[nt]);
                MMA16816(acc[mt][nt], al[mt], bhf[nt]);
            }
    }

    // epilogue: mask + store fp32 scores
    const int erow = lane >> 2;
    const int ecol = (lane & 3) * 2;
    float* Sb = S + (size_t)bh * Sc * Sc;
#pragma unroll
    for (int mt = 0; mt < 2; mt++) {
#pragma unroll
        for (int nt = 0; nt < 8; nt++) {
            const int n = n0 + wn * 64 + nt * 8 + ecol;
            const bool mk0 = (mask[b * Sc + n] == 0);
            const bool mk1 = (mask[b * Sc + n + 1] == 0);
#pragma unroll
            for (int half = 0; half < 2; half++) {
                const int m = m0 + wm * 32 + mt * 16 + erow + half * 8;
                float2 v;
                v.x = mk0 ? -1e9f : acc[mt][nt][half * 2 + 0];
                v.y = mk1 ? -1e9f : acc[mt][nt][half * 2 + 1];
                *(float2*)&Sb[(size_t)m * Sc + n] = v;
            }
        }
    }
}

// ===========================================================================
// softmax kernel: in-place row softmax over gmem. grid = 65536, block = 256
// ===========================================================================
__global__ __launch_bounds__(256) void softmax_kernel(float* __restrict__ S)
{
    __shared__ float red[8];
    const int tid = threadIdx.x;
    float* row = S + (size_t)blockIdx.x * 1024;

    float v[4];
    float mx = -3.4e38f;
#pragma unroll
    for (int i = 0; i < 4; i++) { v[i] = row[tid + i * 256]; mx = fmaxf(mx, v[i]); }
#pragma unroll
    for (int o = 16; o; o >>= 1) mx = fmaxf(mx, __shfl_xor_sync(~0u, mx, o));
    if ((tid & 31) == 0) red[tid >> 5] = mx;
    __syncthreads();
    if (tid < 32) {
        float t = (tid < 8) ? red[tid] : -3.4e38f;
#pragma unroll
        for (int o = 4; o; o >>= 1) t = fmaxf(t, __shfl_xor_sync(~0u, t, o));
        if (tid == 0) red[0] = t;
    }
    __syncthreads();
    mx = red[0];
    __syncthreads();

    float sum = 0.f;
#pragma unroll
    for (int i = 0; i < 4; i++) { v[i] = expf(v[i] - mx); sum += v[i]; }
#pragma unroll
    for (int o = 16; o; o >>= 1) sum += __shfl_xor_sync(~0u, sum, o);
    if ((tid & 31) == 0) red[tid >> 5] = sum;
    __syncthreads();
    if (tid < 32) {
        float t = (tid < 8) ? red[tid] : 0.f;
#pragma unroll
        for (int o = 4; o; o >>= 1) t += __shfl_xor_sync(~0u, t, o);
        if (tid == 0) red[0] = t;
    }
    __syncthreads();
    const float inv = 1.f / red[0];
#pragma unroll
    for (int i = 0; i < 4; i++) row[tid + i * 256] = v[i] * inv;
}

// ===========================================================================
// ctx kernel: ctx[b,q,h*64+d] = sum_k P[bh][q][k] * V[bh][k][d]
// P fp32 from gmem (converted to fp16 on load), V fp16 transposed [bh][d][k].
// Tile 128(m) x 64(n), K streamed in 64-chunks, double buffered.
// Output: bf16 hi/lo split directly. grid (8, 64), block 256.
// ===========================================================================
#define CX_AROWB 144                         // 72 halfs padded row
#define CX_ATILEB (128 * CX_AROWB)           // 18432
#define CX_BTILEB (64 * CX_AROWB)            // 9216
#define CX_STAGEB (CX_ATILEB + CX_BTILEB)    // 27648
#define CX_SMEM_SZ (2 * CX_STAGEB)           // 55296

__global__ __launch_bounds__(256, 1)
void ctx_kernel(const float* __restrict__ P,
                unsigned short* __restrict__ Chi, unsigned short* __restrict__ Clo)
{
    extern __shared__ char smem[];
    const uint32_t sb = smem_to_u32(smem);
    const int tid = threadIdx.x;
    const int wid = tid >> 5, lane = tid & 31;
    const int wm = wid & 3, wn = wid >> 2;
    const int bh = blockIdx.y, b = bh >> 4, h = bh & 15;
    const int m0 = blockIdx.x * 128;

    const float* Pb = P + (size_t)bh * Sc * Sc;
    const __half* Vb = g_VT + (size_t)bh * (Dk * Sc);

    const int arow = tid >> 1, ahalf = tid & 1;   // A: 128 rows x 64 fp32 (2 thr/row)
    float4 a4[8];

    auto ldA = [&](int kt) {
        const float4* g = (const float4*)(Pb + (size_t)(m0 + arow) * 1024 + kt * 64 + ahalf * 32);
#pragma unroll
        for (int i = 0; i < 8; i++) a4[i] = g[i];
    };
    auto stA = [&](int stg) {
        uint32_t sm = sb + stg * CX_STAGEB + arow * CX_AROWB + ahalf * 64;
#pragma unroll
        for (int st = 0; st < 4; st++) {
            __half2 h0 = __floats2half2_rn(a4[st * 2].x, a4[st * 2].y);
            __half2 h1 = __floats2half2_rn(a4[st * 2].z, a4[st * 2].w);
            __half2 h2 = __floats2half2_rn(a4[st * 2 + 1].x, a4[st * 2 + 1].y);
            __half2 h3 = __floats2half2_rn(a4[st * 2 + 1].z, a4[st * 2 + 1].w);
            uint4 u;
            u.x = *(uint32_t*)&h0; u.y = *(uint32_t*)&h1;
            u.z = *(uint32_t*)&h2; u.w = *(uint32_t*)&h3;
            asm volatile("st.shared.v4.b32 [%0], {%1,%2,%3,%4};"
                :: "r"(sm + st * 16), "r"(u.x), "r"(u.y), "r"(u.z), "r"(u.w) : "memory");
        }
    };
    auto loadB = [&](int stg, int kt) {
        if (tid < 128) {
            const int brow = tid >> 1, bhalf = tid & 1;
            const __half* g = Vb + (size_t)brow * 1024 + kt * 64 + bhalf * 32;
            uint32_t sm = sb + stg * CX_STAGEB + CX_ATILEB + brow * CX_AROWB + bhalf * 64;
#pragma unroll
            for (int i = 0; i < 4; i++)
                CP_ASYNC16(sm + i * 16, g + i * 8);
        }
        CP_COMMIT();
    };

    float acc[2][4][4];
#pragma unroll
    for (int mt = 0; mt < 2; mt++)
#pragma unroll
        for (int nt = 0; nt < 4; nt++)
#pragma unroll
            for (int j = 0; j < 4; j++) acc[mt][nt][j] = 0.f;

    const int lg = lane >> 3, lr = lane & 7;
    const int rowoff = (lg & 1) * 8 + lr;
    const uint32_t kquad = (lg >> 1) * 16;

    // prologue
    ldA(0); loadB(0, 0); stA(0);
    CP_WAIT0();
    __syncthreads();

    for (int t = 0; t < 16; t++) {
        const int buf = t & 1;
        if (t + 1 < 16) { ldA(t + 1); loadB(buf ^ 1, t + 1); }

        const uint32_t sA = sb + buf * CX_STAGEB;
        const uint32_t sB = sA + CX_ATILEB;
#pragma unroll
        for (int ks = 0; ks < 4; ks++) {
            const uint32_t kb = ks * 32 + kquad;
            uint32_t af[2][4];
#pragma unroll
            for (int mt = 0; mt < 2; mt++) {
                uint32_t r = (wm * 32 + mt * 16 + rowoff) * CX_AROWB + kb;
                LDMATRIX_X4(af[mt][0], af[mt][1], af[mt][2], af[mt][3], sA + r);
            }
            uint32_t bf[4][2];
#pragma unroll
            for (int p = 0; p < 2; p++) {
                uint32_t r = (wn * 32 + p * 16 + rowoff) * CX_AROWB + kb;
                LDMATRIX_X4(bf[2 * p][0], bf[2 * p + 1][0],
                            bf[2 * p][1], bf[2 * p + 1][1], sB + r);
            }
#pragma unroll
            for (int mt = 0; mt < 2; mt++)
#pragma unroll
                for (int nt = 0; nt < 4; nt++)
                    MMA16816F16(acc[mt][nt], af[mt], bf[nt]);
        }
        if (t + 1 < 16) {
            stA(buf ^ 1);
            CP_WAIT0();
        }
        __syncthreads();
    }

    // epilogue: bf16 hi/lo split -> g_ch/g_cl at [(b*1024+q)][h*64+d]
    const int erow = lane >> 2;
    const int ecol = (lane & 3) * 2;
#pragma unroll
    for (int mt = 0; mt < 2; mt++) {
#pragma unroll
        for (int nt = 0; nt < 4; nt++) {
            const int d = wn * 32 + nt * 8 + ecol;
#pragma unroll
            for (int half = 0; half < 2; half++) {
                const int q = m0 + wm * 32 + mt * 16 + erow + half * 8;
                float v0 = acc[mt][nt][half * 2 + 0];
                float v1 = acc[mt][nt][half * 2 + 1];
                __nv_bfloat16 h0 = __float2bfloat16_rn(v0);
                __nv_bfloat16 h1 = __float2bfloat16_rn(v1);
                __nv_bfloat16 l0 = __float2bfloat16_rn(v0 - __bfloat162float(h0));
                __nv_bfloat16 l1 = __float2bfloat16_rn(v1 - __bfloat162float(h1));
                const size_t idx = ((size_t)(b * Sc) + q) * 1024 + h * Dk + d;
                ushort2 uh; uh.x = __bfloat16_as_ushort(h0); uh.y = __bfloat16_as_ushort(h1);
                ushort2 ul; ul.x = __bfloat16_as_ushort(l0); ul.y = __bfloat16_as_ushort(l1);
                *(ushort2*)&Chi[idx] = uh;
                *(ushort2*)&Clo[idx] = ul;
            }
        }
    }
}

// ===========================================================================
// LayerNorm
// ===========================================================================
__global__ __launch_bounds__(256) void ln_kernel(
    const float* __restrict__ X, const float* __restrict__ gamma,
    const float* __restrict__ beta, float* __restrict__ out)
{
    __shared__ float red1[8];
    __shared__ float red2[8];
    const int row = blockIdx.x;
    const int tid = threadIdx.x;
    const float* x = X + (size_t)row * 1024;

    float v[4];
    float s = 0.f;
#pragma unroll
    for (int i = 0; i < 4; i++) { v[i] = x[tid + i * 256]; s += v[i]; }
#pragma unroll
    for (int o = 16; o; o >>= 1) s += __shfl_xor_sync(~0u, s, o);
    if ((tid & 31) == 0) red1[tid >> 5] = s;
    __syncthreads();
    if (tid < 32) {
        float t = (tid < 8) ? red1[tid] : 0.f;
#pragma unroll
        for (int o = 4; o; o >>= 1) t += __shfl_xor_sync(~0u, t, o);
        if (tid == 0) red1[0] = t;
    }
    __syncthreads();
    const float mu = red1[0] * (1.f / 1024.f);

    float ss = 0.f;
#pragma unroll
    for (int i = 0; i < 4; i++) { float d = v[i] - mu; ss += d * d; }
#pragma unroll
    for (int o = 16; o; o >>= 1) ss += __shfl_xor_sync(~0u, ss, o);
    if ((tid & 31) == 0) red2[tid >> 5] = ss;
    __syncthreads();
    if (tid < 32) {
        float t = (tid < 8) ? red2[tid] : 0.f;
#pragma unroll
        for (int o = 4; o; o >>= 1) t += __shfl_xor_sync(~0u, t, o);
        if (tid == 0) red2[0] = t;
    }
    __syncthreads();
    const float var = red2[0] * (1.f / 1024.f);
    const float rs = rsqrtf(var + 1e-5f);

#pragma unroll
    for (int i = 0; i < 4; i++) {
        const int c = tid + i * 256;
        out[(size_t)row * 1024 + c] = (v[i] - mu) * rs * gamma[c] + beta[c];
    }
}

// ===========================================================================
// Launch
// ===========================================================================
extern "C" void kernel_launch(void* const* d_in, const int* in_sizes, int n_in,
                              void* d_out, int out_size)
{
    const float* memory = (const float*)d_in[0];
    const float* dec    = (const float*)d_in[1];
    const int*   mask   = (const int*)d_in[2];
    const float* Wq = (const float*)d_in[3];
    const float* bq = (const float*)d_in[4];
    const float* Wk = (const float*)d_in[5];
    const float* bk = (const float*)d_in[6];
    const float* Wv = (const float*)d_in[7];
    const float* bv = (const float*)d_in[8];
    const float* Wo = (const float*)d_in[9];
    const float* bo = (const float*)d_in[10];
    const float* gamma = (const float*)d_in[11];
    const float* beta  = (const float*)d_in[12];

    float* out  = (float*)d_out;
    float* attn = out + (size_t)Bc * Sc * Dm;

    void *pX, *pmh, *pml, *pdh, *pdl, *pch, *pcl;
    cudaGetSymbolAddress(&pX, g_X);
    cudaGetSymbolAddress(&pmh, g_mh); cudaGetSymbolAddress(&pml, g_ml);
    cudaGetSymbolAddress(&pdh, g_dh); cudaGetSymbolAddress(&pdl, g_dl);
    cudaGetSymbolAddress(&pch, g_ch); cudaGetSymbolAddress(&pcl, g_cl);
    void *pqh, *pql, *pkh, *pkl, *pvh, *pvl, *poh, *pol;
    cudaGetSymbolAddress(&pqh, g_WqTh); cudaGetSymbolAddress(&pql, g_WqTl);
    cudaGetSymbolAddress(&pkh, g_WkTh); cudaGetSymbolAddress(&pkl, g_WkTl);
    cudaGetSymbolAddress(&pvh, g_WvTh); cudaGetSymbolAddress(&pvl, g_WvTl);
    cudaGetSymbolAddress(&poh, g_WoTh); cudaGetSymbolAddress(&pol, g_WoTl);
    void *pQh, *pQl, *pKh, *pKl, *pVT;
    cudaGetSymbolAddress(&pQh, g_Qh); cudaGetSymbolAddress(&pQl, g_Ql);
    cudaGetSymbolAddress(&pKh, g_Kh); cudaGetSymbolAddress(&pKl, g_Kl);
    cudaGetSymbolAddress(&pVT, g_VT);

    const int NACT4 = Bc * Sc * Dm / 4;

    // ---- prep ----
    split_kernel<<<NACT4 / 256, 256>>>(memory, (unsigned short*)pmh, (unsigned short*)pml, NACT4);
    split_kernel<<<NACT4 / 256, 256>>>(dec,    (unsigned short*)pdh, (unsigned short*)pdl, NACT4);
    transsplit_kernel<<<dim3(16, 16), 256>>>(Wq, (unsigned short*)pqh, (unsigned short*)pql);
    transsplit_kernel<<<dim3(16, 16), 256>>>(Wk, (unsigned short*)pkh, (unsigned short*)pkl);
    transsplit_kernel<<<dim3(16, 16), 256>>>(Wv, (unsigned short*)pvh, (unsigned short*)pvl);
    transsplit_kernel<<<dim3(16, 16), 256>>>(Wo, (unsigned short*)poh, (unsigned short*)pol);

    // ---- projections ----
    cudaFuncSetAttribute(gemm_mma<0>, cudaFuncAttributeMaxDynamicSharedMemorySize, GT_SMEM_SZ);
    cudaFuncSetAttribute(gemm_mma<1>, cudaFuncAttributeMaxDynamicSharedMemorySize, GT_SMEM_SZ);
    cudaFuncSetAttribute(gemm_mma<2>, cudaFuncAttributeMaxDynamicSharedMemorySize, GT_SMEM_SZ);
    const dim3 gg(8, 32), gt(256);
    gemm_mma<0><<<gg, gt, GT_SMEM_SZ>>>((unsigned short*)pmh, (unsigned short*)pml,
                                        (unsigned short*)pqh, (unsigned short*)pql,
                                        bq, nullptr, pQh, pQl, 0.125f);
    gemm_mma<0><<<gg, gt, GT_SMEM_SZ>>>((unsigned short*)pmh, (unsigned short*)pml,
                                        (unsigned short*)pkh, (unsigned short*)pkl,
                                        bk, nullptr, pKh, pKl, 1.0f);
    gemm_mma<2><<<gg, gt, GT_SMEM_SZ>>>((unsigned short*)pdh, (unsigned short*)pdl,
                                        (unsigned short*)pvh, (unsigned short*)pvl,
                                        bv, nullptr, pVT, nullptr, 1.0f);

    // ---- attention: scores -> softmax -> ctx ----
    cudaFuncSetAttribute(scores_kernel, cudaFuncAttributeMaxDynamicSharedMemorySize, SC_SMEM_SZ);
    scores_kernel<<<dim3(8, 8, Bc * Hc), 256, SC_SMEM_SZ>>>(mask, attn);

    softmax_kernel<<<Bc * Hc * Sc, 256>>>(attn);

    cudaFuncSetAttribute(ctx_kernel, cudaFuncAttributeMaxDynamicSharedMemorySize, CX_SMEM_SZ);
    ctx_kernel<<<dim3(8, Bc * Hc), 256, CX_SMEM_SZ>>>(attn, (unsigned short*)pch,
                                                      (unsigned short*)pcl);

    // ---- output projection + residual, then LayerNorm ----
    gemm_mma<1><<<gg, gt, GT_SMEM_SZ>>>((unsigned short*)pch, (unsigned short*)pcl,
                                        (unsigned short*)poh, (unsigned short*)pol,
                                        bo, memory, pX, nullptr, 1.0f);
    ln_kernel<<<Bc * Sc, 256>>>((const float*)pX, gamma, beta, out);
}